// round 8
// baseline (speedup 1.0000x reference)
#include <cuda_runtime.h>
#include <cstdint>
#include <math.h>

#define BATCH 8
#define SEQQ  1024
#define SEQK  1024
#define DM    512
#define NH    8
#define DH    64

// Intermediates (allocation-free: __device__ globals)
__device__ float g_Qp[BATCH * SEQQ * DM];
__device__ float g_Kp[BATCH * SEQK * DM];
__device__ float g_Vp[BATCH * SEQK * DM];
__device__ float g_O [BATCH * SEQQ * DM];

// ---------------------------------------------------------------------------
// helpers
// ---------------------------------------------------------------------------
__device__ __forceinline__ uint32_t f2tf(float x) {
    uint32_t r;
    asm("cvt.rna.tf32.f32 %0, %1;" : "=r"(r) : "f"(x));
    return r;
}

__device__ __forceinline__ void mma_tf32(float d[4], const uint32_t a[4],
                                         const uint32_t b[2]) {
    asm volatile(
        "mma.sync.aligned.m16n8k8.row.col.f32.tf32.tf32.f32 "
        "{%0,%1,%2,%3}, {%4,%5,%6,%7}, {%8,%9}, {%0,%1,%2,%3};"
        : "+f"(d[0]), "+f"(d[1]), "+f"(d[2]), "+f"(d[3])
        : "r"(a[0]), "r"(a[1]), "r"(a[2]), "r"(a[3]), "r"(b[0]), "r"(b[1]));
}

__device__ __forceinline__ void cpasync16(void* smem, const void* g) {
    uint32_t sa = (uint32_t)__cvta_generic_to_shared(smem);
    asm volatile("cp.async.cg.shared.global [%0], [%1], 16;" ::"r"(sa), "l"(g));
}
__device__ __forceinline__ void cp_commit() {
    asm volatile("cp.async.commit_group;");
}

// ---------------------------------------------------------------------------
// GEMM: C[M x 512] = A[M x 512] @ W^T + bias
// SPLIT=2: 2xTF32 (A split hi/lo)   SPLIT=1: 1xTF32 (plain)
// MODE 0: C = A@W^T + b             MODE 1: C = res + relu(A@W^T + b)
// CTA tile 128x64, BK=32, 256 threads, 8 warps as 4(m) x 2(n).
// ---------------------------------------------------------------------------
#define GPITCH 36
#define GSTG   (128 * GPITCH + 64 * GPITCH)   // floats per stage = 6912

template <int MODE, int SPLIT>
__global__ void __launch_bounds__(256, 2) gemm512(
    const float* __restrict__ A, const float* __restrict__ W,
    const float* __restrict__ bias, const float* __restrict__ res,
    float* __restrict__ C)
{
    extern __shared__ float sm[];
    const int tid = threadIdx.x;
    const int lane = tid & 31;
    const int wid = tid >> 5;
    const int warp_m = wid >> 1;
    const int warp_n = wid & 1;
    const int m0 = blockIdx.y * 128;
    const int n0 = blockIdx.x * 64;

    float acc[2][4][4] = {};

    auto load_stage = [&](int t) {
        float* As = sm + (t & 1) * GSTG;
        float* Bs = As + 128 * GPITCH;
        int k0 = t * 32;
        #pragma unroll
        for (int i = 0; i < 4; i++) {
            int idx = tid + i * 256;
            int r = idx >> 3, c4 = idx & 7;
            cpasync16(&As[r * GPITCH + c4 * 4],
                      &A[(size_t)(m0 + r) * 512 + k0 + c4 * 4]);
        }
        #pragma unroll
        for (int i = 0; i < 2; i++) {
            int idx = tid + i * 256;
            int r = idx >> 3, c4 = idx & 7;
            cpasync16(&Bs[r * GPITCH + c4 * 4],
                      &W[(size_t)(n0 + r) * 512 + k0 + c4 * 4]);
        }
        cp_commit();
    };

    load_stage(0);

    for (int t = 0; t < 16; t++) {
        if (t + 1 < 16) {
            load_stage(t + 1);
            asm volatile("cp.async.wait_group 1;");
        } else {
            asm volatile("cp.async.wait_group 0;");
        }
        __syncthreads();

        float* As = sm + (t & 1) * GSTG;
        float* Bs = As + 128 * GPITCH;

        #pragma unroll
        for (int ks = 0; ks < 4; ks++) {
            const int kk = ks * 8;
            uint32_t ah[2][4], al[2][4], bh[4][2];
            #pragma unroll
            for (int mt = 0; mt < 2; mt++) {
                int r = warp_m * 32 + mt * 16 + (lane >> 2);
                const float* p = &As[r * GPITCH + kk + (lane & 3)];
                float x0 = p[0], x1 = p[8 * GPITCH], x2 = p[4], x3 = p[8 * GPITCH + 4];
                ah[mt][0] = f2tf(x0);
                ah[mt][1] = f2tf(x1);
                ah[mt][2] = f2tf(x2);
                ah[mt][3] = f2tf(x3);
                if (SPLIT == 2) {
                    al[mt][0] = f2tf(x0 - __uint_as_float(ah[mt][0]));
                    al[mt][1] = f2tf(x1 - __uint_as_float(ah[mt][1]));
                    al[mt][2] = f2tf(x2 - __uint_as_float(ah[mt][2]));
                    al[mt][3] = f2tf(x3 - __uint_as_float(ah[mt][3]));
                }
            }
            #pragma unroll
            for (int nt = 0; nt < 4; nt++) {
                int n = warp_n * 32 + nt * 8 + (lane >> 2);
                const float* p = &Bs[n * GPITCH + kk + (lane & 3)];
                bh[nt][0] = f2tf(p[0]);
                bh[nt][1] = f2tf(p[4]);
            }
            #pragma unroll
            for (int mt = 0; mt < 2; mt++)
                #pragma unroll
                for (int nt = 0; nt < 4; nt++) {
                    if (SPLIT == 2) mma_tf32(acc[mt][nt], al[mt], bh[nt]);
                    mma_tf32(acc[mt][nt], ah[mt], bh[nt]);
                }
        }
        __syncthreads();
    }

    #pragma unroll
    for (int nt = 0; nt < 4; nt++) {
        int col = n0 + warp_n * 32 + nt * 8 + 2 * (lane & 3);
        float b0 = bias[col], b1 = bias[col + 1];
        #pragma unroll
        for (int mt = 0; mt < 2; mt++) {
            int row = m0 + warp_m * 32 + mt * 16 + (lane >> 2);
            float v00 = acc[mt][nt][0] + b0, v01 = acc[mt][nt][1] + b1;
            float v10 = acc[mt][nt][2] + b0, v11 = acc[mt][nt][3] + b1;
            if (MODE == 1) {
                const float* r0 = &res[(size_t)row * 512 + col];
                const float* r1 = &res[(size_t)(row + 8) * 512 + col];
                v00 = r0[0] + fmaxf(v00, 0.0f);
                v01 = r0[1] + fmaxf(v01, 0.0f);
                v10 = r1[0] + fmaxf(v10, 0.0f);
                v11 = r1[1] + fmaxf(v11, 0.0f);
            }
            *(float2*)&C[(size_t)row * 512 + col]       = make_float2(v00, v01);
            *(float2*)&C[(size_t)(row + 8) * 512 + col] = make_float2(v10, v11);
        }
    }
}

// ---------------------------------------------------------------------------
// Flash attention, CTA = 64 q-rows x 64-key tiles (round-3 shape, measured
// best), with round-7's verified instruction reductions: TF32 pre-conversion
// in smem, column-pair permutation -> uint2 fragment loads, register softmax.
// 8 warps as 2(m) x 4(n): warp tile 32x16. Residual Q read from gmem.
// ---------------------------------------------------------------------------
#define AP 68

__global__ void __launch_bounds__(256, 3) attn_kernel(
    const float* __restrict__ Qp, const float* __restrict__ Kp,
    const float* __restrict__ Vp, float* __restrict__ O)
{
    extern __shared__ uint32_t smu[];
    uint32_t* Qw = smu;                  // 64 x 68, tf32, permuted
    uint32_t* Kw = smu + 64 * AP;        // 64 x 68, tf32, permuted
    uint32_t* Vw = smu + 2 * 64 * AP;    // 64 x 68, tf32, raw layout
    uint32_t* Sw = smu + 3 * 64 * AP;    // 64 x 68, tf32, permuted (P)
    float* Qf = (float*)Qw;
    float* Kf = (float*)Kw;
    float* Vf = (float*)Vw;
    float* pmf = (float*)(smu + 4 * 64 * AP);  // [4][64]
    float* psf = pmf + 256;                    // [4][64]
    float* smm = psf + 256;                    // [64]
    float* sml = smm + 64;                     // [64]

    const int tid = threadIdx.x, lane = tid & 31, wid = tid >> 5;
    const int warp_m = wid >> 2;          // 0..1 (32 q-rows each)
    const int warp_n = wid & 3;           // 0..3 (16 cols each)
    const int qrb = warp_m * 32 + (lane >> 2);
    const int cc = 2 * (lane & 3);
    // permuted positions of (cc, cc+1) within an 8-column block
    const int p0 = ((cc & 3) << 1) | ((cc >> 2) & 1);
    const int p1 = (((cc + 1) & 3) << 1) | (((cc + 1) >> 2) & 1);

    const int q0 = blockIdx.x * 64;
    const int h = blockIdx.y, b = blockIdx.z;
    const float scale = 0.044194173824159216f;  // 1/sqrt(512)

    const float* Qbase = Qp + (size_t)b * SEQQ * DM + h * DH;
    const float* Kbase = Kp + (size_t)b * SEQK * DM + h * DH;
    const float* Vbase = Vp + (size_t)b * SEQK * DM + h * DH;

    // ---- Q: cp.async own blocks -> own-wait -> in-place tf32 + permute ----
    #pragma unroll
    for (int i = 0; i < 2; i++) {
        int bid = tid + i * 256;          // 0..511 (64 rows x 8 blocks)
        int r = bid >> 3, blk = bid & 7;
        cpasync16(&Qf[r * AP + blk * 8],     &Qbase[(size_t)(q0 + r) * DM + blk * 8]);
        cpasync16(&Qf[r * AP + blk * 8 + 4], &Qbase[(size_t)(q0 + r) * DM + blk * 8 + 4]);
    }
    cp_commit();
    if (tid < 64) { smm[tid] = -1e30f; sml[tid] = 0.0f; }
    asm volatile("cp.async.wait_group 0;");
    #pragma unroll
    for (int i = 0; i < 2; i++) {
        int bid = tid + i * 256;
        int r = bid >> 3, blk = bid & 7;
        int base = r * AP + blk * 8;
        float4 in0 = *(float4*)&Qf[base];
        float4 in1 = *(float4*)&Qf[base + 4];
        uint4 o0 = make_uint4(f2tf(in0.x), f2tf(in1.x), f2tf(in0.y), f2tf(in1.y));
        uint4 o1 = make_uint4(f2tf(in0.z), f2tf(in1.z), f2tf(in0.w), f2tf(in1.w));
        *(uint4*)&Qw[base]     = o0;
        *(uint4*)&Qw[base + 4] = o1;
    }

    float oacc[2][2][4] = {};

    for (int kt = 0; kt < SEQK; kt += 64) {
        __syncthreads();   // previous tile fully consumed; Q/stat init visible

        // K (permuted) and V (raw): cp.async own blocks -> own-wait -> convert
        #pragma unroll
        for (int i = 0; i < 2; i++) {
            int bid = tid + i * 256;      // 0..511 (64 rows x 8 blocks)
            int r = bid >> 3, blk = bid & 7;
            cpasync16(&Kf[r * AP + blk * 8],     &Kbase[(size_t)(kt + r) * DM + blk * 8]);
            cpasync16(&Kf[r * AP + blk * 8 + 4], &Kbase[(size_t)(kt + r) * DM + blk * 8 + 4]);
        }
        #pragma unroll
        for (int i = 0; i < 4; i++) {
            int idx = tid + i * 256;      // 0..1023 (64 rows x 16 float4)
            int r = idx >> 4, c4 = idx & 15;
            cpasync16(&Vf[r * AP + c4 * 4], &Vbase[(size_t)(kt + r) * DM + c4 * 4]);
        }
        cp_commit();
        asm volatile("cp.async.wait_group 0;");
        #pragma unroll
        for (int i = 0; i < 2; i++) {
            int bid = tid + i * 256;
            int r = bid >> 3, blk = bid & 7;
            int base = r * AP + blk * 8;
            float4 in0 = *(float4*)&Kf[base];
            float4 in1 = *(float4*)&Kf[base + 4];
            uint4 o0 = make_uint4(f2tf(in0.x), f2tf(in1.x), f2tf(in0.y), f2tf(in1.y));
            uint4 o1 = make_uint4(f2tf(in0.z), f2tf(in1.z), f2tf(in0.w), f2tf(in1.w));
            *(uint4*)&Kw[base]     = o0;
            *(uint4*)&Kw[base + 4] = o1;
        }
        #pragma unroll
        for (int i = 0; i < 4; i++) {
            int idx = tid + i * 256;
            int r = idx >> 4, c4 = idx & 15;
            int base = r * AP + c4 * 4;
            float4 in0 = *(float4*)&Vf[base];
            *(uint4*)&Vw[base] =
                make_uint4(f2tf(in0.x), f2tf(in0.y), f2tf(in0.z), f2tf(in0.w));
        }
        __syncthreads();

        // ---- S = Q @ K^T (uint2 fragment loads, no cvt) ----
        float sfr[2][2][4] = {};
        #pragma unroll
        for (int ks = 0; ks < 8; ks++) {
            int kk = ks * 8;
            uint32_t a[2][4];
            #pragma unroll
            for (int mt = 0; mt < 2; mt++) {
                int r = qrb + mt * 16;
                uint2 lo = *(uint2*)&Qw[r * AP + kk + cc];
                uint2 hi = *(uint2*)&Qw[(r + 8) * AP + kk + cc];
                a[mt][0] = lo.x; a[mt][1] = hi.x; a[mt][2] = lo.y; a[mt][3] = hi.y;
            }
            #pragma unroll
            for (int nt = 0; nt < 2; nt++) {
                int n = warp_n * 16 + nt * 8 + (lane >> 2);
                uint2 bv = *(uint2*)&Kw[n * AP + kk + cc];
                uint32_t bb[2] = {bv.x, bv.y};
                mma_tf32(sfr[0][nt], a[0], bb);
                mma_tf32(sfr[1][nt], a[1], bb);
            }
        }
        #pragma unroll
        for (int mt = 0; mt < 2; mt++)
            #pragma unroll
            for (int nt = 0; nt < 2; nt++)
                #pragma unroll
                for (int j = 0; j < 4; j++)
                    sfr[mt][nt][j] *= scale;

        // ---- partial row max (regs + quad shfl), publish per warp_n ----
        #pragma unroll
        for (int mt = 0; mt < 2; mt++) {
            #pragma unroll
            for (int hh = 0; hh < 2; hh++) {
                float mx = fmaxf(fmaxf(sfr[mt][0][2*hh], sfr[mt][0][2*hh+1]),
                                 fmaxf(sfr[mt][1][2*hh], sfr[mt][1][2*hh+1]));
                mx = fmaxf(mx, __shfl_xor_sync(0xffffffffu, mx, 1));
                mx = fmaxf(mx, __shfl_xor_sync(0xffffffffu, mx, 2));
                if ((lane & 3) == 0)
                    pmf[warp_n * 64 + qrb + mt * 16 + hh * 8] = mx;
            }
        }
        __syncthreads();

        // ---- exp in regs, partial sums, P store (tf32 perm), acc rescale ----
        float mnew[2][2], corr[2][2], rs[2][2];
        #pragma unroll
        for (int mt = 0; mt < 2; mt++)
            #pragma unroll
            for (int hh = 0; hh < 2; hh++) {
                int row = qrb + mt * 16 + hh * 8;
                float mo = smm[row];
                float mn = fmaxf(fmaxf(mo, fmaxf(pmf[row], pmf[64 + row])),
                                 fmaxf(pmf[128 + row], pmf[192 + row]));
                mnew[mt][hh] = mn;
                corr[mt][hh] = __expf(mo - mn);
                rs[mt][hh] = 0.0f;
            }
        #pragma unroll
        for (int mt = 0; mt < 2; mt++)
            #pragma unroll
            for (int nt = 0; nt < 2; nt++) {
                sfr[mt][nt][0] = __expf(sfr[mt][nt][0] - mnew[mt][0]);
                sfr[mt][nt][1] = __expf(sfr[mt][nt][1] - mnew[mt][0]);
                sfr[mt][nt][2] = __expf(sfr[mt][nt][2] - mnew[mt][1]);
                sfr[mt][nt][3] = __expf(sfr[mt][nt][3] - mnew[mt][1]);
                rs[mt][0] += sfr[mt][nt][0] + sfr[mt][nt][1];
                rs[mt][1] += sfr[mt][nt][2] + sfr[mt][nt][3];
            }
        #pragma unroll
        for (int mt = 0; mt < 2; mt++)
            #pragma unroll
            for (int hh = 0; hh < 2; hh++) {
                float s = rs[mt][hh];
                s += __shfl_xor_sync(0xffffffffu, s, 1);
                s += __shfl_xor_sync(0xffffffffu, s, 2);
                if ((lane & 3) == 0)
                    psf[warp_n * 64 + qrb + mt * 16 + hh * 8] = s;
            }
        #pragma unroll
        for (int mt = 0; mt < 2; mt++)
            #pragma unroll
            for (int nt = 0; nt < 2; nt++) {
                oacc[mt][nt][0] *= corr[mt][0]; oacc[mt][nt][1] *= corr[mt][0];
                oacc[mt][nt][2] *= corr[mt][1]; oacc[mt][nt][3] *= corr[mt][1];
            }
        #pragma unroll
        for (int mt = 0; mt < 2; mt++) {
            int r = qrb + mt * 16;
            #pragma unroll
            for (int nt = 0; nt < 2; nt++) {
                int cb = warp_n * 16 + nt * 8;
                Sw[r * AP + cb + p0]       = f2tf(sfr[mt][nt][0]);
                Sw[r * AP + cb + p1]       = f2tf(sfr[mt][nt][1]);
                Sw[(r + 8) * AP + cb + p0] = f2tf(sfr[mt][nt][2]);
                Sw[(r + 8) * AP + cb + p1] = f2tf(sfr[mt][nt][3]);
            }
        }
        __syncthreads();

        // ---- global stats update (m, l) ----
        if (tid < 64) {
            float mo = smm[tid];
            float mn = fmaxf(fmaxf(mo, fmaxf(pmf[tid], pmf[64 + tid])),
                             fmaxf(pmf[128 + tid], pmf[192 + tid]));
            sml[tid] = sml[tid] * __expf(mo - mn) +
                       psf[tid] + psf[64 + tid] + psf[128 + tid] + psf[192 + tid];
            smm[tid] = mn;
        }

        // ---- acc += P @ V ----
        #pragma unroll
        for (int ks = 0; ks < 8; ks++) {
            int kk = ks * 8;
            uint32_t a[2][4];
            #pragma unroll
            for (int mt = 0; mt < 2; mt++) {
                int r = qrb + mt * 16;
                uint2 lo = *(uint2*)&Sw[r * AP + kk + cc];
                uint2 hi = *(uint2*)&Sw[(r + 8) * AP + kk + cc];
                a[mt][0] = lo.x; a[mt][1] = hi.x; a[mt][2] = lo.y; a[mt][3] = hi.y;
            }
            #pragma unroll
            for (int nt = 0; nt < 2; nt++) {
                int n = warp_n * 16 + nt * 8 + (lane >> 2);
                uint32_t bb[2];
                bb[0] = Vw[(kk + (lane & 3)) * AP + n];
                bb[1] = Vw[(kk + 4 + (lane & 3)) * AP + n];
                mma_tf32(oacc[0][nt], a[0], bb);
                mma_tf32(oacc[1][nt], a[1], bb);
            }
        }
    }

    __syncthreads();

    // epilogue: O = Qh (fp32, from gmem) + ctx / l
    float* Obase = O + (size_t)b * SEQQ * DM + h * DH;
    #pragma unroll
    for (int mt = 0; mt < 2; mt++) {
        int r = qrb + mt * 16;
        float inv0 = 1.0f / sml[r];
        float inv1 = 1.0f / sml[r + 8];
        #pragma unroll
        for (int nt = 0; nt < 2; nt++) {
            int cb = warp_n * 16 + nt * 8;
            float2 qv0 = *(const float2*)&Qbase[(size_t)(q0 + r) * DM + cb + cc];
            float2 qv1 = *(const float2*)&Qbase[(size_t)(q0 + r + 8) * DM + cb + cc];
            *(float2*)&Obase[(size_t)(q0 + r) * DM + cb + cc] =
                make_float2(qv0.x + oacc[mt][nt][0] * inv0,
                            qv0.y + oacc[mt][nt][1] * inv0);
            *(float2*)&Obase[(size_t)(q0 + r + 8) * DM + cb + cc] =
                make_float2(qv1.x + oacc[mt][nt][2] * inv1,
                            qv1.y + oacc[mt][nt][3] * inv1);
        }
    }
}

// ---------------------------------------------------------------------------
extern "C" void kernel_launch(void* const* d_in, const int* in_sizes, int n_in,
                              void* d_out, int out_size)
{
    const float* Q  = (const float*)d_in[0];
    const float* K  = (const float*)d_in[1];
    const float* Wq = (const float*)d_in[2];
    const float* bq = (const float*)d_in[3];
    const float* Wk = (const float*)d_in[4];
    const float* bk = (const float*)d_in[5];
    const float* Wv = (const float*)d_in[6];
    const float* bv = (const float*)d_in[7];
    const float* Wo = (const float*)d_in[8];
    const float* bo = (const float*)d_in[9];
    float* out = (float*)d_out;

    float *Qp, *Kp, *Vp, *O;
    cudaGetSymbolAddress((void**)&Qp, g_Qp);
    cudaGetSymbolAddress((void**)&Kp, g_Kp);
    cudaGetSymbolAddress((void**)&Vp, g_Vp);
    cudaGetSymbolAddress((void**)&O,  g_O);

    const int smem_gemm = 2 * GSTG * sizeof(float);                 // 55296 B
    const int smem_attn = (4 * 64 * AP + 640) * 4;                  // 72192 B
    cudaFuncSetAttribute(gemm512<0, 1>,
                         cudaFuncAttributeMaxDynamicSharedMemorySize, smem_gemm);
    cudaFuncSetAttribute(gemm512<1, 2>,
                         cudaFuncAttributeMaxDynamicSharedMemorySize, smem_gemm);
    cudaFuncSetAttribute(attn_kernel,
                         cudaFuncAttributeMaxDynamicSharedMemorySize, smem_attn);

    dim3 gemm_grid(512 / 64, (BATCH * SEQQ) / 128);   // (8, 64)
    gemm512<0, 1><<<gemm_grid, 256, smem_gemm>>>(Q, Wq, bq, nullptr, Qp);
    gemm512<0, 1><<<gemm_grid, 256, smem_gemm>>>(K, Wk, bk, nullptr, Kp);
    gemm512<0, 1><<<gemm_grid, 256, smem_gemm>>>(K, Wv, bv, nullptr, Vp);

    attn_kernel<<<dim3(SEQQ / 64, NH, BATCH), 256, smem_attn>>>(Qp, Kp, Vp, O);

    gemm512<1, 2><<<gemm_grid, 256, smem_gemm>>>(O, Wo, bo, O, out);
}

// round 12
// speedup vs baseline: 1.3353x; 1.3353x over previous
#include <cuda_runtime.h>
#include <cstdint>
#include <math.h>

#define BATCH 8
#define SEQQ  1024
#define SEQK  1024
#define DM    512
#define NH    8
#define DH    64

// Intermediates (allocation-free: __device__ globals)
__device__ float g_Qp[BATCH * SEQQ * DM];
__device__ float g_Kp[BATCH * SEQK * DM];
__device__ float g_Vp[BATCH * SEQK * DM];
__device__ float g_O [BATCH * SEQQ * DM];

// ---------------------------------------------------------------------------
// helpers
// ---------------------------------------------------------------------------
__device__ __forceinline__ uint32_t f2tf(float x) {
    uint32_t r;
    asm("cvt.rna.tf32.f32 %0, %1;" : "=r"(r) : "f"(x));
    return r;
}

__device__ __forceinline__ void mma_tf32(float d[4], const uint32_t a[4],
                                         const uint32_t b[2]) {
    asm volatile(
        "mma.sync.aligned.m16n8k8.row.col.f32.tf32.tf32.f32 "
        "{%0,%1,%2,%3}, {%4,%5,%6,%7}, {%8,%9}, {%0,%1,%2,%3};"
        : "+f"(d[0]), "+f"(d[1]), "+f"(d[2]), "+f"(d[3])
        : "r"(a[0]), "r"(a[1]), "r"(a[2]), "r"(a[3]), "r"(b[0]), "r"(b[1]));
}

__device__ __forceinline__ void cpasync16(void* smem, const void* g) {
    uint32_t sa = (uint32_t)__cvta_generic_to_shared(smem);
    asm volatile("cp.async.cg.shared.global [%0], [%1], 16;" ::"r"(sa), "l"(g));
}
__device__ __forceinline__ void cp_commit() {
    asm volatile("cp.async.commit_group;");
}

// ---------------------------------------------------------------------------
// GEMM: C[M x 512] = A[M x 512] @ W^T + bias
// SPLIT=2: 2xTF32 (A split hi/lo)   SPLIT=1: 1xTF32 (plain)
// MODE 0: C = A@W^T + b             MODE 1: C = res + relu(A@W^T + b)
// CTA tile 128x64, BK=32, 256 threads, 8 warps as 4(m) x 2(n).
// ---------------------------------------------------------------------------
#define GPITCH 36
#define GSTG   (128 * GPITCH + 64 * GPITCH)   // floats per stage = 6912

template <int MODE, int SPLIT>
__global__ void __launch_bounds__(256, 2) gemm512(
    const float* __restrict__ A, const float* __restrict__ W,
    const float* __restrict__ bias, const float* __restrict__ res,
    float* __restrict__ C)
{
    extern __shared__ float sm[];
    const int tid = threadIdx.x;
    const int lane = tid & 31;
    const int wid = tid >> 5;
    const int warp_m = wid >> 1;
    const int warp_n = wid & 1;
    const int m0 = blockIdx.y * 128;
    const int n0 = blockIdx.x * 64;

    float acc[2][4][4] = {};

    auto load_stage = [&](int t) {
        float* As = sm + (t & 1) * GSTG;
        float* Bs = As + 128 * GPITCH;
        int k0 = t * 32;
        #pragma unroll
        for (int i = 0; i < 4; i++) {
            int idx = tid + i * 256;
            int r = idx >> 3, c4 = idx & 7;
            cpasync16(&As[r * GPITCH + c4 * 4],
                      &A[(size_t)(m0 + r) * 512 + k0 + c4 * 4]);
        }
        #pragma unroll
        for (int i = 0; i < 2; i++) {
            int idx = tid + i * 256;
            int r = idx >> 3, c4 = idx & 7;
            cpasync16(&Bs[r * GPITCH + c4 * 4],
                      &W[(size_t)(n0 + r) * 512 + k0 + c4 * 4]);
        }
        cp_commit();
    };

    load_stage(0);

    for (int t = 0; t < 16; t++) {
        if (t + 1 < 16) {
            load_stage(t + 1);
            asm volatile("cp.async.wait_group 1;");
        } else {
            asm volatile("cp.async.wait_group 0;");
        }
        __syncthreads();

        float* As = sm + (t & 1) * GSTG;
        float* Bs = As + 128 * GPITCH;

        #pragma unroll
        for (int ks = 0; ks < 4; ks++) {
            const int kk = ks * 8;
            uint32_t ah[2][4], al[2][4], bh[4][2];
            #pragma unroll
            for (int mt = 0; mt < 2; mt++) {
                int r = warp_m * 32 + mt * 16 + (lane >> 2);
                const float* p = &As[r * GPITCH + kk + (lane & 3)];
                float x0 = p[0], x1 = p[8 * GPITCH], x2 = p[4], x3 = p[8 * GPITCH + 4];
                ah[mt][0] = f2tf(x0);
                ah[mt][1] = f2tf(x1);
                ah[mt][2] = f2tf(x2);
                ah[mt][3] = f2tf(x3);
                if (SPLIT == 2) {
                    al[mt][0] = f2tf(x0 - __uint_as_float(ah[mt][0]));
                    al[mt][1] = f2tf(x1 - __uint_as_float(ah[mt][1]));
                    al[mt][2] = f2tf(x2 - __uint_as_float(ah[mt][2]));
                    al[mt][3] = f2tf(x3 - __uint_as_float(ah[mt][3]));
                }
            }
            #pragma unroll
            for (int nt = 0; nt < 4; nt++) {
                int n = warp_n * 32 + nt * 8 + (lane >> 2);
                const float* p = &Bs[n * GPITCH + kk + (lane & 3)];
                bh[nt][0] = f2tf(p[0]);
                bh[nt][1] = f2tf(p[4]);
            }
            #pragma unroll
            for (int mt = 0; mt < 2; mt++)
                #pragma unroll
                for (int nt = 0; nt < 4; nt++) {
                    if (SPLIT == 2) mma_tf32(acc[mt][nt], al[mt], bh[nt]);
                    mma_tf32(acc[mt][nt], ah[mt], bh[nt]);
                }
        }
        __syncthreads();
    }

    #pragma unroll
    for (int nt = 0; nt < 4; nt++) {
        int col = n0 + warp_n * 32 + nt * 8 + 2 * (lane & 3);
        float b0 = bias[col], b1 = bias[col + 1];
        #pragma unroll
        for (int mt = 0; mt < 2; mt++) {
            int row = m0 + warp_m * 32 + mt * 16 + (lane >> 2);
            float v00 = acc[mt][nt][0] + b0, v01 = acc[mt][nt][1] + b1;
            float v10 = acc[mt][nt][2] + b0, v11 = acc[mt][nt][3] + b1;
            if (MODE == 1) {
                const float* r0 = &res[(size_t)row * 512 + col];
                const float* r1 = &res[(size_t)(row + 8) * 512 + col];
                v00 = r0[0] + fmaxf(v00, 0.0f);
                v01 = r0[1] + fmaxf(v01, 0.0f);
                v10 = r1[0] + fmaxf(v10, 0.0f);
                v11 = r1[1] + fmaxf(v11, 0.0f);
            }
            *(float2*)&C[(size_t)row * 512 + col]       = make_float2(v00, v01);
            *(float2*)&C[(size_t)(row + 8) * 512 + col] = make_float2(v10, v11);
        }
    }
}

// ---------------------------------------------------------------------------
// Flash attention: round-3 structure (measured 213us) — float smem, inline
// f2tf in fragment loads, NO pre-conversion passes — plus round-8's
// register softmax (removes the S smem read-modify-write pass).
// CTA = 64 q-rows x 64-key tiles; 8 warps as 2(m) x 4(n), warp tile 32x16.
// ---------------------------------------------------------------------------
#define AP 68

__global__ void __launch_bounds__(256, 3) attn_kernel(
    const float* __restrict__ Qp, const float* __restrict__ Kp,
    const float* __restrict__ Vp, float* __restrict__ O)
{
    extern __shared__ float smf[];
    float* Qs = smf;                 // 64 x 68 fp32
    float* Ks = smf + 64 * AP;       // 64 x 68 fp32
    float* Vs = smf + 2 * 64 * AP;   // 64 x 68 fp32
    float* Ss = smf + 3 * 64 * AP;   // 64 x 68 fp32 (P)
    float* pmf = smf + 4 * 64 * AP;  // [4][64] partial max per warp_n
    float* psf = pmf + 256;          // [4][64] partial sum per warp_n
    float* smm = psf + 256;          // [64] running max
    float* sml = smm + 64;           // [64] running denom

    const int tid = threadIdx.x, lane = tid & 31, wid = tid >> 5;
    const int warp_m = wid >> 2;          // 0..1 (32 q-rows each)
    const int warp_n = wid & 3;           // 0..3 (16 cols each)
    const int qrb = warp_m * 32 + (lane >> 2);

    const int q0 = blockIdx.x * 64;
    const int h = blockIdx.y, b = blockIdx.z;
    const float scale = 0.044194173824159216f;  // 1/sqrt(512)

    const float* Qbase = Qp + (size_t)b * SEQQ * DM + h * DH;
    const float* Kbase = Kp + (size_t)b * SEQK * DM + h * DH;
    const float* Vbase = Vp + (size_t)b * SEQK * DM + h * DH;

    // load Q tile [64 x 64] (fp32, straight cp.async)
    #pragma unroll
    for (int i = 0; i < 4; i++) {
        int idx = tid + i * 256;          // float4 index
        int r = idx >> 4, c4 = idx & 15;
        cpasync16(&Qs[r * AP + c4 * 4], &Qbase[(size_t)(q0 + r) * DM + c4 * 4]);
    }
    cp_commit();
    if (tid < 64) { smm[tid] = -1e30f; sml[tid] = 0.0f; }

    float oacc[2][2][4] = {};

    for (int kt = 0; kt < SEQK; kt += 64) {
        __syncthreads();   // previous tile consumed; Q/stat init visible
        #pragma unroll
        for (int i = 0; i < 4; i++) {
            int idx = tid + i * 256;
            int r = idx >> 4, c4 = idx & 15;
            cpasync16(&Ks[r * AP + c4 * 4], &Kbase[(size_t)(kt + r) * DM + c4 * 4]);
            cpasync16(&Vs[r * AP + c4 * 4], &Vbase[(size_t)(kt + r) * DM + c4 * 4]);
        }
        cp_commit();
        asm volatile("cp.async.wait_group 0;");
        __syncthreads();

        // ---- S = Q @ K^T (inline tf32 cvt in fragment loads) ----
        float sfr[2][2][4] = {};
        #pragma unroll
        for (int ks = 0; ks < 8; ks++) {
            const int kk = ks * 8;
            uint32_t af[2][4], bf[2][2];
            #pragma unroll
            for (int mt = 0; mt < 2; mt++) {
                int r = qrb + mt * 16;
                const float* p = &Qs[r * AP + kk + (lane & 3)];
                af[mt][0] = f2tf(p[0]);
                af[mt][1] = f2tf(p[8 * AP]);
                af[mt][2] = f2tf(p[4]);
                af[mt][3] = f2tf(p[8 * AP + 4]);
            }
            #pragma unroll
            for (int nt = 0; nt < 2; nt++) {
                int n = warp_n * 16 + nt * 8 + (lane >> 2);
                const float* p = &Ks[n * AP + kk + (lane & 3)];
                bf[nt][0] = f2tf(p[0]);
                bf[nt][1] = f2tf(p[4]);
            }
            #pragma unroll
            for (int mt = 0; mt < 2; mt++)
                #pragma unroll
                for (int nt = 0; nt < 2; nt++)
                    mma_tf32(sfr[mt][nt], af[mt], bf[nt]);
        }
        #pragma unroll
        for (int mt = 0; mt < 2; mt++)
            #pragma unroll
            for (int nt = 0; nt < 2; nt++)
                #pragma unroll
                for (int j = 0; j < 4; j++)
                    sfr[mt][nt][j] *= scale;

        // ---- partial row max (regs + quad shfl), publish per warp_n ----
        #pragma unroll
        for (int mt = 0; mt < 2; mt++) {
            #pragma unroll
            for (int hh = 0; hh < 2; hh++) {
                float mx = fmaxf(fmaxf(sfr[mt][0][2*hh], sfr[mt][0][2*hh+1]),
                                 fmaxf(sfr[mt][1][2*hh], sfr[mt][1][2*hh+1]));
                mx = fmaxf(mx, __shfl_xor_sync(0xffffffffu, mx, 1));
                mx = fmaxf(mx, __shfl_xor_sync(0xffffffffu, mx, 2));
                if ((lane & 3) == 0)
                    pmf[warp_n * 64 + qrb + mt * 16 + hh * 8] = mx;
            }
        }
        __syncthreads();

        // ---- exp in regs, partial sums, P store (fp32), acc rescale ----
        float mnew[2][2], corr[2][2], rs[2][2];
        #pragma unroll
        for (int mt = 0; mt < 2; mt++)
            #pragma unroll
            for (int hh = 0; hh < 2; hh++) {
                int row = qrb + mt * 16 + hh * 8;
                float mo = smm[row];
                float mn = fmaxf(fmaxf(mo, fmaxf(pmf[row], pmf[64 + row])),
                                 fmaxf(pmf[128 + row], pmf[192 + row]));
                mnew[mt][hh] = mn;
                corr[mt][hh] = __expf(mo - mn);
                rs[mt][hh] = 0.0f;
            }
        #pragma unroll
        for (int mt = 0; mt < 2; mt++)
            #pragma unroll
            for (int nt = 0; nt < 2; nt++) {
                sfr[mt][nt][0] = __expf(sfr[mt][nt][0] - mnew[mt][0]);
                sfr[mt][nt][1] = __expf(sfr[mt][nt][1] - mnew[mt][0]);
                sfr[mt][nt][2] = __expf(sfr[mt][nt][2] - mnew[mt][1]);
                sfr[mt][nt][3] = __expf(sfr[mt][nt][3] - mnew[mt][1]);
                rs[mt][0] += sfr[mt][nt][0] + sfr[mt][nt][1];
                rs[mt][1] += sfr[mt][nt][2] + sfr[mt][nt][3];
            }
        #pragma unroll
        for (int mt = 0; mt < 2; mt++)
            #pragma unroll
            for (int hh = 0; hh < 2; hh++) {
                float s = rs[mt][hh];
                s += __shfl_xor_sync(0xffffffffu, s, 1);
                s += __shfl_xor_sync(0xffffffffu, s, 2);
                if ((lane & 3) == 0)
                    psf[warp_n * 64 + qrb + mt * 16 + hh * 8] = s;
            }
        #pragma unroll
        for (int mt = 0; mt < 2; mt++)
            #pragma unroll
            for (int nt = 0; nt < 2; nt++) {
                oacc[mt][nt][0] *= corr[mt][0]; oacc[mt][nt][1] *= corr[mt][0];
                oacc[mt][nt][2] *= corr[mt][1]; oacc[mt][nt][3] *= corr[mt][1];
            }
        #pragma unroll
        for (int mt = 0; mt < 2; mt++) {
            int r = qrb + mt * 16;
            #pragma unroll
            for (int nt = 0; nt < 2; nt++) {
                int c = warp_n * 16 + nt * 8 + 2 * (lane & 3);
                *(float2*)&Ss[r * AP + c] =
                    make_float2(sfr[mt][nt][0], sfr[mt][nt][1]);
                *(float2*)&Ss[(r + 8) * AP + c] =
                    make_float2(sfr[mt][nt][2], sfr[mt][nt][3]);
            }
        }
        __syncthreads();

        // ---- global stats update (m, l) ----
        if (tid < 64) {
            float mo = smm[tid];
            float mn = fmaxf(fmaxf(mo, fmaxf(pmf[tid], pmf[64 + tid])),
                             fmaxf(pmf[128 + tid], pmf[192 + tid]));
            sml[tid] = sml[tid] * __expf(mo - mn) +
                       psf[tid] + psf[64 + tid] + psf[128 + tid] + psf[192 + tid];
            smm[tid] = mn;
        }

        // ---- acc += P @ V ----
        #pragma unroll
        for (int ks = 0; ks < 8; ks++) {
            const int kk = ks * 8;
            uint32_t af[2][4], bf[2][2];
            #pragma unroll
            for (int mt = 0; mt < 2; mt++) {
                int r = qrb + mt * 16;
                const float* p = &Ss[r * AP + kk + (lane & 3)];
                af[mt][0] = f2tf(p[0]);
                af[mt][1] = f2tf(p[8 * AP]);
                af[mt][2] = f2tf(p[4]);
                af[mt][3] = f2tf(p[8 * AP + 4]);
            }
            #pragma unroll
            for (int nt = 0; nt < 2; nt++) {
                int n = warp_n * 16 + nt * 8 + (lane >> 2);
                const float* p = &Vs[(kk + (lane & 3)) * AP + n];
                bf[nt][0] = f2tf(p[0]);
                bf[nt][1] = f2tf(p[4 * AP]);
            }
            #pragma unroll
            for (int mt = 0; mt < 2; mt++)
                #pragma unroll
                for (int nt = 0; nt < 2; nt++)
                    mma_tf32(oacc[mt][nt], af[mt], bf[nt]);
        }
    }
    __syncthreads();

    // epilogue: O = Qh (fp32 from Qs) + ctx / l
    float* Obase = O + (size_t)b * SEQQ * DM + h * DH;
    #pragma unroll
    for (int mt = 0; mt < 2; mt++) {
        int r = qrb + mt * 16;
        float inv0 = 1.0f / sml[r];
        float inv1 = 1.0f / sml[r + 8];
        #pragma unroll
        for (int nt = 0; nt < 2; nt++) {
            int c = warp_n * 16 + nt * 8 + 2 * (lane & 3);
            float q00 = Qs[r * AP + c],       q01 = Qs[r * AP + c + 1];
            float q10 = Qs[(r + 8) * AP + c], q11 = Qs[(r + 8) * AP + c + 1];
            *(float2*)&Obase[(size_t)(q0 + r) * DM + c] =
                make_float2(q00 + oacc[mt][nt][0] * inv0,
                            q01 + oacc[mt][nt][1] * inv0);
            *(float2*)&Obase[(size_t)(q0 + r + 8) * DM + c] =
                make_float2(q10 + oacc[mt][nt][2] * inv1,
                            q11 + oacc[mt][nt][3] * inv1);
        }
    }
}

// ---------------------------------------------------------------------------
extern "C" void kernel_launch(void* const* d_in, const int* in_sizes, int n_in,
                              void* d_out, int out_size)
{
    const float* Q  = (const float*)d_in[0];
    const float* K  = (const float*)d_in[1];
    const float* Wq = (const float*)d_in[2];
    const float* bq = (const float*)d_in[3];
    const float* Wk = (const float*)d_in[4];
    const float* bk = (const float*)d_in[5];
    const float* Wv = (const float*)d_in[6];
    const float* bv = (const float*)d_in[7];
    const float* Wo = (const float*)d_in[8];
    const float* bo = (const float*)d_in[9];
    float* out = (float*)d_out;

    float *Qp, *Kp, *Vp, *O;
    cudaGetSymbolAddress((void**)&Qp, g_Qp);
    cudaGetSymbolAddress((void**)&Kp, g_Kp);
    cudaGetSymbolAddress((void**)&Vp, g_Vp);
    cudaGetSymbolAddress((void**)&O,  g_O);

    const int smem_gemm = 2 * GSTG * sizeof(float);                 // 55296 B
    const int smem_attn = (4 * 64 * AP + 640) * 4;                  // 72192 B
    cudaFuncSetAttribute(gemm512<0, 1>,
                         cudaFuncAttributeMaxDynamicSharedMemorySize, smem_gemm);
    cudaFuncSetAttribute(gemm512<1, 1>,
                         cudaFuncAttributeMaxDynamicSharedMemorySize, smem_gemm);
    cudaFuncSetAttribute(attn_kernel,
                         cudaFuncAttributeMaxDynamicSharedMemorySize, smem_attn);

    dim3 gemm_grid(512 / 64, (BATCH * SEQQ) / 128);   // (8, 64)
    gemm512<0, 1><<<gemm_grid, 256, smem_gemm>>>(Q, Wq, bq, nullptr, Qp);
    gemm512<0, 1><<<gemm_grid, 256, smem_gemm>>>(K, Wk, bk, nullptr, Kp);
    gemm512<0, 1><<<gemm_grid, 256, smem_gemm>>>(K, Wv, bv, nullptr, Vp);

    attn_kernel<<<dim3(SEQQ / 64, NH, BATCH), 256, smem_attn>>>(Qp, Kp, Vp, O);

    gemm512<1, 1><<<gemm_grid, 256, smem_gemm>>>(O, Wo, bo, O, out);
}